// round 8
// baseline (speedup 1.0000x reference)
#include <cuda_runtime.h>
#include <math.h>
#include <stdint.h>
#include <cuda_bf16.h>

// ---------------- problem constants ----------------
#define S_LEN 2048
#define HID_D 2048
#define H_NUM 16
#define QLR_D 1536
#define KVLR_D 512
#define NOPE_D 128
#define ROPE_D 64
#define VD_D   128
#define QKD_D  192
#define QF_D   576

#define ATTN_SCALE 0.07216878364870323f

// ---------------- scratch ----------------
__device__ float g_qa   [S_LEN * QLR_D];
__device__ float g_q    [S_LEN * H_NUM * QKD_D];
__device__ float g_kva  [S_LEN * (KVLR_D + ROPE_D)];
__device__ float g_qfull[S_LEN * H_NUM * QF_D];
__device__ float g_kfull[S_LEN * QF_D];
__device__ float g_kfullT[QF_D * S_LEN];                    // [c][t]
__device__ float g_scores[(size_t)H_NUM * S_LEN * S_LEN];
__device__ float g_attn [S_LEN * H_NUM * KVLR_D];
__device__ float g_oflat[S_LEN * H_NUM * VD_D];

// pre-rounded (tf32) copies of inputs
__device__ float g_x_r   [S_LEN * HID_D];
__device__ float g_wqa_r [QLR_D * HID_D];
__device__ float g_wqb_r [H_NUM * QKD_D * QLR_D];
__device__ float g_wkva_r[(KVLR_D + ROPE_D) * HID_D];
__device__ float g_wkvb_r[H_NUM * (NOPE_D + VD_D) * KVLR_D];
__device__ float g_wkvbT_r[H_NUM * KVLR_D * NOPE_D];        // [h][c][d] nope^T
__device__ float g_wo_r  [HID_D * H_NUM * VD_D];

// ---------------- tf32 helpers ----------------
__device__ __forceinline__ uint32_t f2tf32(float f) {
    uint32_t u;
    asm("cvt.rna.tf32.f32 %0, %1;" : "=r"(u) : "f"(f));
    return u;
}
__device__ __forceinline__ float round_tf32(float f) {
    return __uint_as_float(f2tf32(f));
}

__device__ __forceinline__ void mma_tf32(float* d,
    uint32_t a0, uint32_t a1, uint32_t a2, uint32_t a3,
    uint32_t b0, uint32_t b1)
{
    asm volatile(
        "mma.sync.aligned.m16n8k8.row.col.f32.tf32.tf32.f32 "
        "{%0,%1,%2,%3}, {%4,%5,%6,%7}, {%8,%9}, {%0,%1,%2,%3};\n"
        : "+f"(d[0]), "+f"(d[1]), "+f"(d[2]), "+f"(d[3])
        : "r"(a0), "r"(a1), "r"(a2), "r"(a3), "r"(b0), "r"(b1));
}

__device__ __forceinline__ void ldsm_x4(uint32_t& d0, uint32_t& d1,
                                        uint32_t& d2, uint32_t& d3,
                                        uint32_t addr)
{
    asm volatile(
        "ldmatrix.sync.aligned.m8n8.x4.shared.b16 {%0,%1,%2,%3}, [%4];\n"
        : "=r"(d0), "=r"(d1), "=r"(d2), "=r"(d3) : "r"(addr));
}

// ---------------- cp.async helpers ----------------
__device__ __forceinline__ void cp16(uint32_t dst, const float* src, bool ok) {
    int sz = ok ? 16 : 0;
    asm volatile("cp.async.cg.shared.global [%0], [%1], 16, %2;\n"
                 :: "r"(dst), "l"(src), "r"(sz));
}
__device__ __forceinline__ void cp_commit() {
    asm volatile("cp.async.commit_group;\n");
}
__device__ __forceinline__ void cp_wait2() {
    asm volatile("cp.async.wait_group 2;\n");
}

// ---------------- pipelined TF32 tensor-core GEMM (NT only) ----------------
// C[m][n] = alpha * sum_k A[m][k] * B[n][k] (+bias[n]); all operands
// pre-rounded to tf32 in gmem. M % 128 == 0, K % 16 == 0, K/16 >= 4.
// Fragments fetched via ldmatrix on the stride-20 operand-major smem tiles.
#define BM 128
#define BN 128
#define NSTAGE 4
#define STG_STRIDE 5120
#define SMEM_BYTES (NSTAGE * STG_STRIDE * 4)

__global__ __launch_bounds__(256, 2) void mma_gemm(
    int M, int N, int K,
    const float* __restrict__ A, int lda, long long sA,
    const float* __restrict__ B, int ldb, long long sB,
    float*       __restrict__ C, int ldc, long long sC,
    const float* __restrict__ bias, float alpha,
    int causal, int trapezoid, int roundC)
{
    const int row0 = blockIdx.y * BM;
    const int col0 = blockIdx.x * BN;
    if (causal && col0 > row0) return;

    A += (long long)blockIdx.z * sA;
    B += (long long)blockIdx.z * sB;
    C += (long long)blockIdx.z * sC;

    extern __shared__ float smem[];
    const uint32_t smem_base = (uint32_t)__cvta_generic_to_shared(smem);

    const int tid  = threadIdx.x;
    const int lane = tid & 31;
    const int warp = tid >> 5;
    const int wm   = warp & 3;
    const int wn   = warp >> 2;
    const int grp  = lane >> 2;
    const int qid  = lane & 3;

    const int kmax  = trapezoid ? min(K, row0 + BM) : K;
    const int steps = kmax >> 4;

    // ---- per-thread copy geometry (2 x 16B each for A and B) ----
    int am0  = tid >> 2,          akq0 = (tid & 3) << 2;
    int am1  = (tid + 256) >> 2,  akq1 = ((tid + 256) & 3) << 2;
    const float* a_src0 = A + (size_t)(row0 + am0) * lda + akq0;
    const float* a_src1 = A + (size_t)(row0 + am1) * lda + akq1;
    uint32_t a_dst0 = (am0 * 20 + akq0) * 4;
    uint32_t a_dst1 = (am1 * 20 + akq1) * 4;

    int bn0 = tid >> 2,         bkq0 = (tid & 3) << 2;
    int bn1 = (tid + 256) >> 2, bkq1 = ((tid + 256) & 3) << 2;
    bool bok0 = (col0 + bn0) < N;
    bool bok1 = (col0 + bn1) < N;
    const float* b_src0 = B + (size_t)(col0 + bn0) * ldb + bkq0;
    const float* b_src1 = B + (size_t)(col0 + bn1) * ldb + bkq1;
    uint32_t b_dst0 = (2560 + bn0 * 20 + bkq0) * 4;
    uint32_t b_dst1 = (2560 + bn1 * 20 + bkq1) * 4;

    auto issue_stage = [&](int st, int t) {
        uint32_t base = smem_base + st * (STG_STRIDE * 4);
        long long kofs = (long long)t * 16;
        cp16(base + a_dst0, a_src0 + kofs, true);
        cp16(base + a_dst1, a_src1 + kofs, true);
        cp16(base + b_dst0, b_src0 + kofs, bok0);
        cp16(base + b_dst1, b_src1 + kofs, bok1);
    };

    // ---- ldmatrix lane offset (bytes within a tile) ----
    // g = lane>>3 selects submatrix: row += (g>>1)*8, col += (g&1)*4
    const int lg  = lane >> 3;
    const int lli = lane & 7;
    const uint32_t lofs = (((lg >> 1) * 8 + lli) * 20 + (lg & 1) * 4) * 4;

    float acc[2][8][4];
#pragma unroll
    for (int mi = 0; mi < 2; mi++)
#pragma unroll
        for (int ni = 0; ni < 8; ni++)
#pragma unroll
            for (int r = 0; r < 4; r++) acc[mi][ni][r] = 0.f;

#pragma unroll
    for (int t = 0; t < NSTAGE - 1; t++) {
        issue_stage(t, t);
        cp_commit();
    }

    for (int s = 0; s < steps; s++) {
        cp_wait2();
        __syncthreads();

        const uint32_t stage_byte = smem_base + (s & (NSTAGE - 1)) * (STG_STRIDE * 4);

#pragma unroll
        for (int ks = 0; ks < 16; ks += 8) {
            uint32_t bf[8][2];
#pragma unroll
            for (int ni2 = 0; ni2 < 4; ni2++) {
                uint32_t addr = stage_byte +
                    (2560 + (wn * 64 + ni2 * 16) * 20 + ks) * 4 + lofs;
                ldsm_x4(bf[2 * ni2][0], bf[2 * ni2][1],
                        bf[2 * ni2 + 1][0], bf[2 * ni2 + 1][1], addr);
            }
#pragma unroll
            for (int mi = 0; mi < 2; mi++) {
                uint32_t a0, a1, a2, a3;
                uint32_t addr = stage_byte +
                    ((wm * 32 + mi * 16) * 20 + ks) * 4 + lofs;
                ldsm_x4(a0, a2, a1, a3, addr);   // d-order = (a0, a2, a1, a3)
#pragma unroll
                for (int ni = 0; ni < 8; ni++)
                    mma_tf32(acc[mi][ni], a0, a1, a2, a3, bf[ni][0], bf[ni][1]);
            }
        }

        int t = s + NSTAGE - 1;
        if (t < steps)
            issue_stage(t & (NSTAGE - 1), t);
        cp_commit();
    }

    // ---- epilogue ----
#pragma unroll
    for (int mi = 0; mi < 2; mi++) {
        int r = row0 + wm * 32 + mi * 16 + grp;
#pragma unroll
        for (int ni = 0; ni < 8; ni++) {
            int c = col0 + wn * 64 + ni * 8 + 2 * qid;
            if (c < N) {
                float b0 = bias ? bias[c]     : 0.f;
                float b1 = bias ? bias[c + 1] : 0.f;
                float v00 = acc[mi][ni][0] * alpha + b0;
                float v01 = acc[mi][ni][1] * alpha + b1;
                float v10 = acc[mi][ni][2] * alpha + b0;
                float v11 = acc[mi][ni][3] * alpha + b1;
                if (roundC) {
                    v00 = round_tf32(v00); v01 = round_tf32(v01);
                    v10 = round_tf32(v10); v11 = round_tf32(v11);
                }
                *reinterpret_cast<float2*>(&C[(size_t)r * ldc + c]) =
                    make_float2(v00, v01);
                *reinterpret_cast<float2*>(&C[(size_t)(r + 8) * ldc + c]) =
                    make_float2(v10, v11);
            }
        }
    }
}

// ---------------- elementwise tf32 pre-round ----------------
__global__ void round_kernel(const float* __restrict__ in,
                             float* __restrict__ out, int n4)
{
    int i = blockIdx.x * blockDim.x + threadIdx.x;
    if (i < n4) {
        float4 v = reinterpret_cast<const float4*>(in)[i];
        v.x = round_tf32(v.x); v.y = round_tf32(v.y);
        v.z = round_tf32(v.z); v.w = round_tf32(v.w);
        reinterpret_cast<float4*>(out)[i] = v;
    }
}

// ---------------- transpose wkv_b nope -> [h][c][d], rounded ----------------
// in: wkv_b_w[h*256 + d][c] (c<512, d<128)  out: g_wkvbT_r[h][c][d]
__global__ void transpose_wkvb_kernel(const float* __restrict__ in)
{
    __shared__ float tl[32][33];
    int h  = blockIdx.z;
    int bx = blockIdx.x, by = blockIdx.y;
    int tx = threadIdx.x, ty = threadIdx.y;
#pragma unroll
    for (int j = 0; j < 4; j++) {
        int d = by * 32 + ty + j * 8;
        int c = bx * 32 + tx;
        tl[ty + j * 8][tx] = in[(size_t)(h * 256 + d) * KVLR_D + c];
    }
    __syncthreads();
#pragma unroll
    for (int j = 0; j < 4; j++) {
        int c = bx * 32 + ty + j * 8;
        int d = by * 32 + tx;
        g_wkvbT_r[(size_t)h * KVLR_D * NOPE_D + (size_t)c * NOPE_D + d] =
            round_tf32(tl[tx][ty + j * 8]);
    }
}

// ---------------- transpose kfull -> kfullT [c][t] ----------------
__global__ void transpose_kfull_kernel()
{
    __shared__ float tl[32][33];
    int bx = blockIdx.x, by = blockIdx.y;
    int tx = threadIdx.x, ty = threadIdx.y;
#pragma unroll
    for (int j = 0; j < 4; j++) {
        int t = by * 32 + ty + j * 8;
        int c = bx * 32 + tx;
        tl[ty + j * 8][tx] = g_kfull[(size_t)t * QF_D + c];
    }
    __syncthreads();
#pragma unroll
    for (int j = 0; j < 4; j++) {
        int c = bx * 32 + ty + j * 8;
        int t = by * 32 + tx;
        g_kfullT[(size_t)c * S_LEN + t] = tl[tx][ty + j * 8];
    }
}

// ---------------- reductions ----------------
__device__ __forceinline__ float block_reduce_sum(float v) {
    __shared__ float sh[32];
    __syncthreads();
    int lane = threadIdx.x & 31, w = threadIdx.x >> 5;
#pragma unroll
    for (int o = 16; o; o >>= 1) v += __shfl_xor_sync(0xffffffffu, v, o);
    if (lane == 0) sh[w] = v;
    __syncthreads();
    int nw = blockDim.x >> 5;
    v = (threadIdx.x < nw) ? sh[threadIdx.x] : 0.f;
    if (w == 0) {
#pragma unroll
        for (int o = 16; o; o >>= 1) v += __shfl_xor_sync(0xffffffffu, v, o);
        if (lane == 0) sh[0] = v;
    }
    __syncthreads();
    return sh[0];
}

__device__ __forceinline__ float block_reduce_max(float v) {
    __shared__ float sh[32];
    __syncthreads();
    int lane = threadIdx.x & 31, w = threadIdx.x >> 5;
#pragma unroll
    for (int o = 16; o; o >>= 1) v = fmaxf(v, __shfl_xor_sync(0xffffffffu, v, o));
    if (lane == 0) sh[w] = v;
    __syncthreads();
    int nw = blockDim.x >> 5;
    v = (threadIdx.x < nw) ? sh[threadIdx.x] : -INFINITY;
    if (w == 0) {
#pragma unroll
        for (int o = 16; o; o >>= 1) v = fmaxf(v, __shfl_xor_sync(0xffffffffu, v, o));
        if (lane == 0) sh[0] = v;
    }
    __syncthreads();
    return sh[0];
}

// ---------------- rmsnorm (tf32-rounded output) ----------------
__global__ void rmsnorm_kernel(const float* __restrict__ in, int in_ld,
                               float* __restrict__ out, int out_ld,
                               const float* __restrict__ w, int D)
{
    int row = blockIdx.x;
    const float* x = in + (size_t)row * in_ld;
    float* y = out + (size_t)row * out_ld;
    float s = 0.f;
    for (int i = threadIdx.x; i < D; i += blockDim.x) {
        float v = x[i];
        s += v * v;
    }
    s = block_reduce_sum(s);
    float inv = rsqrtf(s / (float)D + 1e-6f);
    for (int i = threadIdx.x; i < D; i += blockDim.x)
        y[i] = round_tf32(w[i] * x[i] * inv);
}

// ---------------- RoPE (tf32-rounded output) ----------------
__device__ __forceinline__ float rope_apply(const float* src, int s, int d) {
    int i = d & 31;
    float inv_freq = expf(-(float)i * (logf(10000.f) / 32.f));
    float ang = (float)s * inv_freq;
    float c = cosf(ang), sn = sinf(ang);
    float x = src[d];
    float rot = (d < 32) ? -src[d + 32] : src[d - 32];
    return x * c + rot * sn;
}

__global__ void rope_k_kernel() {
    int s = blockIdx.x, d = threadIdx.x;
    const float* src = g_kva + (size_t)s * QF_D + KVLR_D;
    g_kfull[(size_t)s * QF_D + KVLR_D + d] = round_tf32(rope_apply(src, s, d));
}

__global__ void rope_q_kernel() {
    int s = blockIdx.x, h = blockIdx.y, d = threadIdx.x;
    const float* src = g_q + (size_t)s * (H_NUM * QKD_D) + h * QKD_D + NOPE_D;
    g_qfull[(size_t)s * (H_NUM * QF_D) + h * QF_D + KVLR_D + d] =
        round_tf32(rope_apply(src, s, d));
}

// ---------------- causal softmax (tf32-rounded probs) ----------------
__global__ void softmax_kernel() {
    int i = blockIdx.x;
    int h = blockIdx.y;
    float* row = g_scores + ((size_t)h * S_LEN + i) * S_LEN;
    int n = i + 1;
    int jmax = ((i >> 7) + 1) << 7;

    float m = -INFINITY;
    for (int j = threadIdx.x; j < n; j += blockDim.x) m = fmaxf(m, row[j]);
    m = block_reduce_max(m);

    float s = 0.f;
    for (int j = threadIdx.x; j < n; j += blockDim.x) {
        float e = expf(row[j] - m);
        row[j] = e;
        s += e;
    }
    s = block_reduce_sum(s);
    float inv = 1.f / s;
    for (int j = threadIdx.x; j < n; j += blockDim.x)
        row[j] = round_tf32(row[j] * inv);
    for (int j = n + threadIdx.x; j < jmax; j += blockDim.x) row[j] = 0.f;
}

// ---------------- host launcher ----------------
static float* sym_addr(const void* sym) {
    void* p = nullptr;
    cudaGetSymbolAddress(&p, sym);
    return (float*)p;
}

extern "C" void kernel_launch(void* const* d_in, const int* in_sizes, int n_in,
                              void* d_out, int out_size)
{
    const float* x        = (const float*)d_in[0];
    const float* wq_a_w   = (const float*)d_in[1];
    const float* wq_a_b   = (const float*)d_in[2];
    const float* q_norm_w = (const float*)d_in[3];
    const float* wq_b_w   = (const float*)d_in[4];
    const float* wq_b_b   = (const float*)d_in[5];
    const float* wkv_a_w  = (const float*)d_in[6];
    const float* wkv_a_b  = (const float*)d_in[7];
    const float* kv_norm_w= (const float*)d_in[8];
    const float* wkv_b_w  = (const float*)d_in[9];
    const float* wo_w     = (const float*)d_in[10];
    const float* wo_b     = (const float*)d_in[11];
    float* out = (float*)d_out;

    float* qa     = sym_addr(g_qa);
    float* q      = sym_addr(g_q);
    float* kva    = sym_addr(g_kva);
    float* qfull  = sym_addr(g_qfull);
    float* kfull  = sym_addr(g_kfull);
    float* kfullT = sym_addr(g_kfullT);
    float* scores = sym_addr(g_scores);
    float* attn   = sym_addr(g_attn);
    float* oflat  = sym_addr(g_oflat);

    float* x_r     = sym_addr(g_x_r);
    float* wqa_r   = sym_addr(g_wqa_r);
    float* wqb_r   = sym_addr(g_wqb_r);
    float* wkva_r  = sym_addr(g_wkva_r);
    float* wkvb_r  = sym_addr(g_wkvb_r);
    float* wkvbT_r = sym_addr(g_wkvbT_r);
    float* wo_r    = sym_addr(g_wo_r);

    cudaFuncSetAttribute(mma_gemm,
        cudaFuncAttributeMaxDynamicSharedMemorySize, SMEM_BYTES);

    dim3 tb(256);
    auto grid = [](int M, int N, int Z) {
        return dim3((N + BN - 1) / BN, (M + BM - 1) / BM, Z);
    };
    auto rnd = [&](const float* src, float* dst, int n) {
        round_kernel<<<(n / 4 + 255) / 256, 256>>>(src, dst, n / 4);
    };

    // 0) pre-round inputs to tf32 (+ transposed nope block of wkv_b)
    rnd(x,       x_r,    S_LEN * HID_D);
    rnd(wq_a_w,  wqa_r,  QLR_D * HID_D);
    rnd(wq_b_w,  wqb_r,  H_NUM * QKD_D * QLR_D);
    rnd(wkv_a_w, wkva_r, (KVLR_D + ROPE_D) * HID_D);
    rnd(wkv_b_w, wkvb_r, H_NUM * (NOPE_D + VD_D) * KVLR_D);
    rnd(wo_w,    wo_r,   HID_D * H_NUM * VD_D);
    transpose_wkvb_kernel<<<dim3(KVLR_D / 32, NOPE_D / 32, H_NUM),
                            dim3(32, 8)>>>(wkv_b_w);

    // 1) q_a = x @ wq_a^T + b
    mma_gemm<<<grid(S_LEN, QLR_D, 1), tb, SMEM_BYTES>>>(
        S_LEN, QLR_D, HID_D, x_r, HID_D, 0, wqa_r, HID_D, 0,
        qa, QLR_D, 0, wq_a_b, 1.f, 0, 0, 0);

    // 2) rmsnorm(q_a) (rounded out)
    rmsnorm_kernel<<<S_LEN, 256>>>(qa, QLR_D, qa, QLR_D, q_norm_w, QLR_D);

    // 3) q = q_a @ wq_b^T + b (round out)
    mma_gemm<<<grid(S_LEN, H_NUM * QKD_D, 1), tb, SMEM_BYTES>>>(
        S_LEN, H_NUM * QKD_D, QLR_D, qa, QLR_D, 0, wqb_r, QLR_D, 0,
        q, H_NUM * QKD_D, 0, wq_b_b, 1.f, 0, 0, 1);

    // 4) kv_a = x @ wkv_a^T + b
    mma_gemm<<<grid(S_LEN, QF_D, 1), tb, SMEM_BYTES>>>(
        S_LEN, QF_D, HID_D, x_r, HID_D, 0, wkva_r, HID_D, 0,
        kva, QF_D, 0, wkv_a_b, 1.f, 0, 0, 0);

    // 5) kv = rmsnorm(kv_a[:, :512]) -> kfull[:, :512] (rounded)
    rmsnorm_kernel<<<S_LEN, 256>>>(kva, QF_D, kfull, QF_D, kv_norm_w, KVLR_D);

    // 6) roped k_pe (rounded)
    rope_k_kernel<<<S_LEN, ROPE_D>>>();

    // 6b) kfullT = kfull^T  (for NT PV GEMM)
    transpose_kfull_kernel<<<dim3(QF_D / 32, S_LEN / 32), dim3(32, 8)>>>();

    // 7) roped q_pe (rounded)
    rope_q_kernel<<<dim3(S_LEN, H_NUM), ROPE_D>>>();

    // 8) q_nope @ wkv_b_nope -> qfull[:, h, :512]  (NT via wkvbT, round out)
    mma_gemm<<<grid(S_LEN, KVLR_D, H_NUM), tb, SMEM_BYTES>>>(
        S_LEN, KVLR_D, NOPE_D,
        q, H_NUM * QKD_D, QKD_D,
        wkvbT_r, NOPE_D, (long long)KVLR_D * NOPE_D,
        qfull, H_NUM * QF_D, QF_D,
        nullptr, 1.f, 0, 0, 1);

    // 9) scores (causal skip)
    mma_gemm<<<grid(S_LEN, S_LEN, H_NUM), tb, SMEM_BYTES>>>(
        S_LEN, S_LEN, QF_D,
        qfull, H_NUM * QF_D, QF_D,
        kfull, QF_D, 0,
        scores, S_LEN, (long long)S_LEN * S_LEN,
        nullptr, ATTN_SCALE, 1, 0, 0);

    // 10) causal softmax (rounded probs)
    softmax_kernel<<<dim3(S_LEN, H_NUM), 256>>>();

    // 11) attn = P @ kv  (NT via kfullT, trapezoidal, round out)
    mma_gemm<<<grid(S_LEN, KVLR_D, H_NUM), tb, SMEM_BYTES>>>(
        S_LEN, KVLR_D, S_LEN,
        scores, S_LEN, (long long)S_LEN * S_LEN,
        kfullT, S_LEN, 0,
        attn, H_NUM * KVLR_D, KVLR_D,
        nullptr, 1.f, 0, 1, 1);

    // 12) o_h = attn_h @ wkv_b_v^T (round out)
    mma_gemm<<<grid(S_LEN, VD_D, H_NUM), tb, SMEM_BYTES>>>(
        S_LEN, VD_D, KVLR_D,
        attn, H_NUM * KVLR_D, KVLR_D,
        wkvb_r + (size_t)NOPE_D * KVLR_D, KVLR_D, (long long)(NOPE_D + VD_D) * KVLR_D,
        oflat, H_NUM * VD_D, VD_D,
        nullptr, 1.f, 0, 0, 1);

    // 13) out = oflat @ wo^T + b (final, no round)
    mma_gemm<<<grid(S_LEN, HID_D, 1), tb, SMEM_BYTES>>>(
        S_LEN, HID_D, H_NUM * VD_D,
        oflat, H_NUM * VD_D, 0,
        wo_r, H_NUM * VD_D, 0,
        out, HID_D, 0, wo_b, 1.f, 0, 0, 0);
}

// round 10
// speedup vs baseline: 1.1640x; 1.1640x over previous
#include <cuda_runtime.h>
#include <math.h>
#include <stdint.h>
#include <cuda_bf16.h>

// ---------------- problem constants ----------------
#define S_LEN 2048
#define HID_D 2048
#define H_NUM 16
#define QLR_D 1536
#define KVLR_D 512
#define NOPE_D 128
#define ROPE_D 64
#define VD_D   128
#define QKD_D  192
#define QF_D   576

#define ATTN_SCALE 0.07216878364870323f

// ---------------- scratch ----------------
__device__ float g_qa   [S_LEN * QLR_D];
__device__ float g_q    [S_LEN * H_NUM * QKD_D];
__device__ float g_kva  [S_LEN * (KVLR_D + ROPE_D)];
__device__ float g_qfull[S_LEN * H_NUM * QF_D];
__device__ float g_kfull[S_LEN * QF_D];
__device__ float g_scores[(size_t)H_NUM * S_LEN * S_LEN];
__device__ float g_attn [S_LEN * H_NUM * KVLR_D];
__device__ float g_oflat[S_LEN * H_NUM * VD_D];

// pre-rounded (tf32) copies of inputs
__device__ float g_x_r   [S_LEN * HID_D];
__device__ float g_wqa_r [QLR_D * HID_D];
__device__ float g_wqb_r [H_NUM * QKD_D * QLR_D];
__device__ float g_wkva_r[(KVLR_D + ROPE_D) * HID_D];
__device__ float g_wkvb_r[H_NUM * (NOPE_D + VD_D) * KVLR_D];
__device__ float g_wo_r  [HID_D * H_NUM * VD_D];

// ---------------- tf32 helpers ----------------
__device__ __forceinline__ uint32_t f2tf32(float f) {
    uint32_t u;
    asm("cvt.rna.tf32.f32 %0, %1;" : "=r"(u) : "f"(f));
    return u;
}
__device__ __forceinline__ float round_tf32(float f) {
    return __uint_as_float(f2tf32(f));
}

__device__ __forceinline__ void mma_tf32(float* d,
    uint32_t a0, uint32_t a1, uint32_t a2, uint32_t a3,
    uint32_t b0, uint32_t b1)
{
    asm volatile(
        "mma.sync.aligned.m16n8k8.row.col.f32.tf32.tf32.f32 "
        "{%0,%1,%2,%3}, {%4,%5,%6,%7}, {%8,%9}, {%0,%1,%2,%3};\n"
        : "+f"(d[0]), "+f"(d[1]), "+f"(d[2]), "+f"(d[3])
        : "r"(a0), "r"(a1), "r"(a2), "r"(a3), "r"(b0), "r"(b1));
}

// ---------------- cp.async helpers ----------------
__device__ __forceinline__ void cp16(uint32_t dst, const float* src, bool ok) {
    int sz = ok ? 16 : 0;
    asm volatile("cp.async.cg.shared.global [%0], [%1], 16, %2;\n"
                 :: "r"(dst), "l"(src), "r"(sz));
}
__device__ __forceinline__ void cp_commit() {
    asm volatile("cp.async.commit_group;\n");
}
__device__ __forceinline__ void cp_wait2() {
    asm volatile("cp.async.wait_group 2;\n");
}

// ---------------- pipelined TF32 tensor-core GEMM ----------------
// All GEMM operands pre-rounded to tf32 in gmem; hot loop has no conversions.
//   BT=true : B' = B[n][k]  (NT)   BT=false: B' = B[k][n]  (NN)
// M % 128 == 0, K % 16 == 0, K/16 >= 4 at every call site.
#define BM 128
#define BN 128
#define NSTAGE 4
#define STG_STRIDE 5120
#define SMEM_BYTES (NSTAGE * STG_STRIDE * 4)

template <bool BT>
__global__ __launch_bounds__(256, 2) void mma_gemm(
    int M, int N, int K,
    const float* __restrict__ A, int lda, long long sA,
    const float* __restrict__ B, int ldb, long long sB,
    float*       __restrict__ C, int ldc, long long sC,
    const float* __restrict__ bias, float alpha,
    int causal, int trapezoid, int roundC)
{
    const int row0 = blockIdx.y * BM;
    const int col0 = blockIdx.x * BN;
    if (causal && col0 > row0) return;

    A += (long long)blockIdx.z * sA;
    B += (long long)blockIdx.z * sB;
    C += (long long)blockIdx.z * sC;

    extern __shared__ float smem[];
    const uint32_t smem_base = (uint32_t)__cvta_generic_to_shared(smem);

    const int tid  = threadIdx.x;
    const int lane = tid & 31;
    const int warp = tid >> 5;
    const int wm   = warp & 3;
    const int wn   = warp >> 2;
    const int grp  = lane >> 2;
    const int qid  = lane & 3;

    const int kmax  = trapezoid ? min(K, row0 + BM) : K;
    const int steps = kmax >> 4;

    // ---- per-thread copy geometry ----
    int am0  = tid >> 2,          akq0 = (tid & 3) << 2;
    int am1  = (tid + 256) >> 2,  akq1 = ((tid + 256) & 3) << 2;
    const float* a_src0 = A + (size_t)(row0 + am0) * lda + akq0;
    const float* a_src1 = A + (size_t)(row0 + am1) * lda + akq1;
    uint32_t a_dst0 = (am0 * 20 + akq0) * 4;
    uint32_t a_dst1 = (am1 * 20 + akq1) * 4;

    const float* b_src0; const float* b_src1;
    uint32_t b_dst0, b_dst1;
    bool bok0, bok1;
    long long b_step;
    if (BT) {
        int n0 = tid >> 2,         kq0 = (tid & 3) << 2;
        int n1 = (tid + 256) >> 2, kq1 = ((tid + 256) & 3) << 2;
        bok0 = (col0 + n0) < N;  bok1 = (col0 + n1) < N;
        b_src0 = B + (size_t)(col0 + n0) * ldb + kq0;
        b_src1 = B + (size_t)(col0 + n1) * ldb + kq1;
        b_dst0 = (2560 + n0 * 20 + kq0) * 4;
        b_dst1 = (2560 + n1 * 20 + kq1) * 4;
        b_step = 16;
    } else {
        int k0i = tid >> 5,          nq0 = (tid & 31) << 2;
        int k1i = (tid + 256) >> 5,  nq1 = ((tid + 256) & 31) << 2;
        bok0 = (col0 + nq0) < N;  bok1 = (col0 + nq1) < N;
        b_src0 = B + (size_t)k0i * ldb + col0 + nq0;
        b_src1 = B + (size_t)k1i * ldb + col0 + nq1;
        b_dst0 = (2560 + k0i * 136 + nq0) * 4;
        b_dst1 = (2560 + k1i * 136 + nq1) * 4;
        b_step = (long long)16 * ldb;
    }

    auto issue_stage = [&](int st, int t) {
        uint32_t base = smem_base + st * (STG_STRIDE * 4);
        long long ka = (long long)t * 16;
        long long kb = (long long)t * b_step;
        cp16(base + a_dst0, a_src0 + ka, true);
        cp16(base + a_dst1, a_src1 + ka, true);
        cp16(base + b_dst0, b_src0 + kb, bok0);
        cp16(base + b_dst1, b_src1 + kb, bok1);
    };

    float acc[2][8][4];
#pragma unroll
    for (int mi = 0; mi < 2; mi++)
#pragma unroll
        for (int ni = 0; ni < 8; ni++)
#pragma unroll
            for (int r = 0; r < 4; r++) acc[mi][ni][r] = 0.f;

#pragma unroll
    for (int t = 0; t < NSTAGE - 1; t++) {
        issue_stage(t, t);
        cp_commit();
    }

    for (int s = 0; s < steps; s++) {
        cp_wait2();
        __syncthreads();

        const uint32_t* Acur = reinterpret_cast<const uint32_t*>(
            smem + (s & (NSTAGE - 1)) * STG_STRIDE);
        const uint32_t* Bcur = Acur + 2560;

#pragma unroll
        for (int ks = 0; ks < 16; ks += 8) {
            uint32_t bf[8][2];
#pragma unroll
            for (int ni = 0; ni < 8; ni++) {
                int c = wn * 64 + ni * 8 + grp;
                if (BT) {
                    bf[ni][0] = Bcur[c * 20 + ks + qid];
                    bf[ni][1] = Bcur[c * 20 + ks + qid + 4];
                } else {
                    bf[ni][0] = Bcur[(ks + qid) * 136 + c];
                    bf[ni][1] = Bcur[(ks + qid + 4) * 136 + c];
                }
            }
#pragma unroll
            for (int mi = 0; mi < 2; mi++) {
                int r = wm * 32 + mi * 16 + grp;
                uint32_t a0 = Acur[r * 20 + ks + qid];
                uint32_t a1 = Acur[(r + 8) * 20 + ks + qid];
                uint32_t a2 = Acur[r * 20 + ks + qid + 4];
                uint32_t a3 = Acur[(r + 8) * 20 + ks + qid + 4];
#pragma unroll
                for (int ni = 0; ni < 8; ni++)
                    mma_tf32(acc[mi][ni], a0, a1, a2, a3, bf[ni][0], bf[ni][1]);
            }
        }

        int t = s + NSTAGE - 1;
        if (t < steps)
            issue_stage(t & (NSTAGE - 1), t);
        cp_commit();
    }

    // ---- epilogue ----
#pragma unroll
    for (int mi = 0; mi < 2; mi++) {
        int r = row0 + wm * 32 + mi * 16 + grp;
#pragma unroll
        for (int ni = 0; ni < 8; ni++) {
            int c = col0 + wn * 64 + ni * 8 + 2 * qid;
            if (c < N) {
                float b0 = bias ? bias[c]     : 0.f;
                float b1 = bias ? bias[c + 1] : 0.f;
                float v00 = acc[mi][ni][0] * alpha + b0;
                float v01 = acc[mi][ni][1] * alpha + b1;
                float v10 = acc[mi][ni][2] * alpha + b0;
                float v11 = acc[mi][ni][3] * alpha + b1;
                if (roundC) {
                    v00 = round_tf32(v00); v01 = round_tf32(v01);
                    v10 = round_tf32(v10); v11 = round_tf32(v11);
                }
                *reinterpret_cast<float2*>(&C[(size_t)r * ldc + c]) =
                    make_float2(v00, v01);
                *reinterpret_cast<float2*>(&C[(size_t)(r + 8) * ldc + c]) =
                    make_float2(v10, v11);
            }
        }
    }
}

// ---------------- elementwise tf32 pre-round ----------------
__global__ void round_kernel(const float* __restrict__ in,
                             float* __restrict__ out, int n4)
{
    int i = blockIdx.x * blockDim.x + threadIdx.x;
    if (i < n4) {
        float4 v = reinterpret_cast<const float4*>(in)[i];
        v.x = round_tf32(v.x); v.y = round_tf32(v.y);
        v.z = round_tf32(v.z); v.w = round_tf32(v.w);
        reinterpret_cast<float4*>(out)[i] = v;
    }
}

// ---------------- reductions ----------------
__device__ __forceinline__ float block_reduce_sum(float v) {
    __shared__ float sh[32];
    __syncthreads();
    int lane = threadIdx.x & 31, w = threadIdx.x >> 5;
#pragma unroll
    for (int o = 16; o; o >>= 1) v += __shfl_xor_sync(0xffffffffu, v, o);
    if (lane == 0) sh[w] = v;
    __syncthreads();
    int nw = blockDim.x >> 5;
    v = (threadIdx.x < nw) ? sh[threadIdx.x] : 0.f;
    if (w == 0) {
#pragma unroll
        for (int o = 16; o; o >>= 1) v += __shfl_xor_sync(0xffffffffu, v, o);
        if (lane == 0) sh[0] = v;
    }
    __syncthreads();
    return sh[0];
}

__device__ __forceinline__ float block_reduce_max(float v) {
    __shared__ float sh[32];
    __syncthreads();
    int lane = threadIdx.x & 31, w = threadIdx.x >> 5;
#pragma unroll
    for (int o = 16; o; o >>= 1) v = fmaxf(v, __shfl_xor_sync(0xffffffffu, v, o));
    if (lane == 0) sh[w] = v;
    __syncthreads();
    int nw = blockDim.x >> 5;
    v = (threadIdx.x < nw) ? sh[threadIdx.x] : -INFINITY;
    if (w == 0) {
#pragma unroll
        for (int o = 16; o; o >>= 1) v = fmaxf(v, __shfl_xor_sync(0xffffffffu, v, o));
        if (lane == 0) sh[0] = v;
    }
    __syncthreads();
    return sh[0];
}

// ---------------- rmsnorm (tf32-rounded output) ----------------
__global__ void rmsnorm_kernel(const float* __restrict__ in, int in_ld,
                               float* __restrict__ out, int out_ld,
                               const float* __restrict__ w, int D)
{
    int row = blockIdx.x;
    const float* x = in + (size_t)row * in_ld;
    float* y = out + (size_t)row * out_ld;
    float s = 0.f;
    for (int i = threadIdx.x; i < D; i += blockDim.x) {
        float v = x[i];
        s += v * v;
    }
    s = block_reduce_sum(s);
    float inv = rsqrtf(s / (float)D + 1e-6f);
    for (int i = threadIdx.x; i < D; i += blockDim.x)
        y[i] = round_tf32(w[i] * x[i] * inv);
}

// ---------------- RoPE (tf32-rounded output) ----------------
__device__ __forceinline__ float rope_apply(const float* src, int s, int d) {
    int i = d & 31;
    float inv_freq = expf(-(float)i * (logf(10000.f) / 32.f));
    float ang = (float)s * inv_freq;
    float c = cosf(ang), sn = sinf(ang);
    float x = src[d];
    float rot = (d < 32) ? -src[d + 32] : src[d - 32];
    return x * c + rot * sn;
}

__global__ void rope_k_kernel() {
    int s = blockIdx.x, d = threadIdx.x;
    const float* src = g_kva + (size_t)s * QF_D + KVLR_D;
    g_kfull[(size_t)s * QF_D + KVLR_D + d] = round_tf32(rope_apply(src, s, d));
}

__global__ void rope_q_kernel() {
    int s = blockIdx.x, h = blockIdx.y, d = threadIdx.x;
    const float* src = g_q + (size_t)s * (H_NUM * QKD_D) + h * QKD_D + NOPE_D;
    g_qfull[(size_t)s * (H_NUM * QF_D) + h * QF_D + KVLR_D + d] =
        round_tf32(rope_apply(src, s, d));
}

// ---------------- single-pass causal softmax ----------------
// Row cached in 8 registers/thread (2048 / 256). One gmem read + one write.
// Zero-fills only to the end of the 128-row diagonal block (PV is trapezoidal).
__global__ void softmax_kernel() {
    int i = blockIdx.x;
    int h = blockIdx.y;
    float* row = g_scores + ((size_t)h * S_LEN + i) * S_LEN;
    int n = i + 1;
    int jmax = ((i >> 7) + 1) << 7;

    float v[8];
    float m = -INFINITY;
#pragma unroll
    for (int r = 0; r < 8; r++) {
        int j = threadIdx.x + (r << 8);
        v[r] = (j < n) ? row[j] : -INFINITY;
        m = fmaxf(m, v[r]);
    }
    m = block_reduce_max(m);

    float s = 0.f;
#pragma unroll
    for (int r = 0; r < 8; r++) {
        float e = expf(v[r] - m);     // exp(-inf) = 0 handles the tail
        v[r] = e;
        s += e;
    }
    s = block_reduce_sum(s);
    float inv = 1.f / s;

#pragma unroll
    for (int r = 0; r < 8; r++) {
        int j = threadIdx.x + (r << 8);
        if (j < jmax)
            row[j] = (j < n) ? round_tf32(v[r] * inv) : 0.f;
    }
}

// ---------------- host launcher ----------------
static float* sym_addr(const void* sym) {
    void* p = nullptr;
    cudaGetSymbolAddress(&p, sym);
    return (float*)p;
}

extern "C" void kernel_launch(void* const* d_in, const int* in_sizes, int n_in,
                              void* d_out, int out_size)
{
    const float* x        = (const float*)d_in[0];
    const float* wq_a_w   = (const float*)d_in[1];
    const float* wq_a_b   = (const float*)d_in[2];
    const float* q_norm_w = (const float*)d_in[3];
    const float* wq_b_w   = (const float*)d_in[4];
    const float* wq_b_b   = (const float*)d_in[5];
    const float* wkv_a_w  = (const float*)d_in[6];
    const float* wkv_a_b  = (const float*)d_in[7];
    const float* kv_norm_w= (const float*)d_in[8];
    const float* wkv_b_w  = (const float*)d_in[9];
    const float* wo_w     = (const float*)d_in[10];
    const float* wo_b     = (const float*)d_in[11];
    float* out = (float*)d_out;

    float* qa    = sym_addr(g_qa);
    float* q     = sym_addr(g_q);
    float* kva   = sym_addr(g_kva);
    float* qfull = sym_addr(g_qfull);
    float* kfull = sym_addr(g_kfull);
    float* scores= sym_addr(g_scores);
    float* attn  = sym_addr(g_attn);
    float* oflat = sym_addr(g_oflat);

    float* x_r    = sym_addr(g_x_r);
    float* wqa_r  = sym_addr(g_wqa_r);
    float* wqb_r  = sym_addr(g_wqb_r);
    float* wkva_r = sym_addr(g_wkva_r);
    float* wkvb_r = sym_addr(g_wkvb_r);
    float* wo_r   = sym_addr(g_wo_r);

    cudaFuncSetAttribute(mma_gemm<true>,
        cudaFuncAttributeMaxDynamicSharedMemorySize, SMEM_BYTES);
    cudaFuncSetAttribute(mma_gemm<false>,
        cudaFuncAttributeMaxDynamicSharedMemorySize, SMEM_BYTES);

    dim3 tb(256);
    auto grid = [](int M, int N, int Z) {
        return dim3((N + BN - 1) / BN, (M + BM - 1) / BM, Z);
    };
    auto rnd = [&](const float* src, float* dst, int n) {
        round_kernel<<<(n / 4 + 255) / 256, 256>>>(src, dst, n / 4);
    };

    // 0) pre-round inputs to tf32
    rnd(x,       x_r,    S_LEN * HID_D);
    rnd(wq_a_w,  wqa_r,  QLR_D * HID_D);
    rnd(wq_b_w,  wqb_r,  H_NUM * QKD_D * QLR_D);
    rnd(wkv_a_w, wkva_r, (KVLR_D + ROPE_D) * HID_D);
    rnd(wkv_b_w, wkvb_r, H_NUM * (NOPE_D + VD_D) * KVLR_D);
    rnd(wo_w,    wo_r,   HID_D * H_NUM * VD_D);

    // 1) q_a = x @ wq_a^T + b
    mma_gemm<true><<<grid(S_LEN, QLR_D, 1), tb, SMEM_BYTES>>>(
        S_LEN, QLR_D, HID_D, x_r, HID_D, 0, wqa_r, HID_D, 0,
        qa, QLR_D, 0, wq_a_b, 1.f, 0, 0, 0);

    // 2) rmsnorm(q_a) (rounded out)
    rmsnorm_kernel<<<S_LEN, 256>>>(qa, QLR_D, qa, QLR_D, q_norm_w, QLR_D);

    // 3) q = q_a @ wq_b^T + b (round out)
    mma_gemm<true><<<grid(S_LEN, H_NUM * QKD_D, 1), tb, SMEM_BYTES>>>(
        S_LEN, H_NUM * QKD_D, QLR_D, qa, QLR_D, 0, wqb_r, QLR_D, 0,
        q, H_NUM * QKD_D, 0, wq_b_b, 1.f, 0, 0, 1);

    // 4) kv_a = x @ wkv_a^T + b
    mma_gemm<true><<<grid(S_LEN, QF_D, 1), tb, SMEM_BYTES>>>(
        S_LEN, QF_D, HID_D, x_r, HID_D, 0, wkva_r, HID_D, 0,
        kva, QF_D, 0, wkv_a_b, 1.f, 0, 0, 0);

    // 5) kv = rmsnorm(kv_a[:, :512]) -> kfull[:, :512] (rounded)
    rmsnorm_kernel<<<S_LEN, 256>>>(kva, QF_D, kfull, QF_D, kv_norm_w, KVLR_D);

    // 6) roped k_pe (rounded)
    rope_k_kernel<<<S_LEN, ROPE_D>>>();

    // 7) roped q_pe (rounded)
    rope_q_kernel<<<dim3(S_LEN, H_NUM), ROPE_D>>>();

    // 8) q_nope @ wkv_b[:, :128, :] -> qfull[:, h, :512]  (NN, round out)
    mma_gemm<false><<<grid(S_LEN, KVLR_D, H_NUM), tb, SMEM_BYTES>>>(
        S_LEN, KVLR_D, NOPE_D,
        q, H_NUM * QKD_D, QKD_D,
        wkvb_r, KVLR_D, (long long)(NOPE_D + VD_D) * KVLR_D,
        qfull, H_NUM * QF_D, QF_D,
        nullptr, 1.f, 0, 0, 1);

    // 9) scores (causal skip)
    mma_gemm<true><<<grid(S_LEN, S_LEN, H_NUM), tb, SMEM_BYTES>>>(
        S_LEN, S_LEN, QF_D,
        qfull, H_NUM * QF_D, QF_D,
        kfull, QF_D, 0,
        scores, S_LEN, (long long)S_LEN * S_LEN,
        nullptr, ATTN_SCALE, 1, 0, 0);

    // 10) single-pass causal softmax (rounded probs)
    softmax_kernel<<<dim3(S_LEN, H_NUM), 256>>>();

    // 11) attn = P @ kv  (NN, trapezoidal, round out)
    mma_gemm<false><<<grid(S_LEN, KVLR_D, H_NUM), tb, SMEM_BYTES>>>(
        S_LEN, KVLR_D, S_LEN,
        scores, S_LEN, (long long)S_LEN * S_LEN,
        kfull, QF_D, 0,
        attn, H_NUM * KVLR_D, KVLR_D,
        nullptr, 1.f, 0, 1, 1);

    // 12) o_h = attn_h @ wkv_b[:, 128:, :]^T (round out)
    mma_gemm<true><<<grid(S_LEN, VD_D, H_NUM), tb, SMEM_BYTES>>>(
        S_LEN, VD_D, KVLR_D,
        attn, H_NUM * KVLR_D, KVLR_D,
        wkvb_r + (size_t)NOPE_D * KVLR_D, KVLR_D, (long long)(NOPE_D + VD_D) * KVLR_D,
        oflat, H_NUM * VD_D, VD_D,
        nullptr, 1.f, 0, 0, 1);

    // 13) out = oflat @ wo^T + b (final, no round)
    mma_gemm<true><<<grid(S_LEN, HID_D, 1), tb, SMEM_BYTES>>>(
        S_LEN, HID_D, H_NUM * VD_D,
        oflat, H_NUM * VD_D, 0,
        wo_r, H_NUM * VD_D, 0,
        out, HID_D, 0, wo_b, 1.f, 0, 0, 0);
}